// round 13
// baseline (speedup 1.0000x reference)
#include <cuda_runtime.h>
#include <cuda_bf16.h>
#include <cstdint>

#define BB 4
#define CC 64
#define FF 64
#define TT 128
#define IC 32
#define NN 8192
#define MM 2048
#define EPSF 1e-5f

// Scratch (device globals; allocation forbidden)
__device__ float  g_q[BB*MM];
__device__ float  g_qs[BB*MM];
__device__ int    g_perm[BB*MM];
__device__ float  g_z[BB*CC*MM];
__device__ float  g_s[BB*NN];
__device__ float2 g_sk[BB*NN];            // (s[n], bitcast k[n])
__device__ float2 g_PQ[BB*CC*(MM+2)];     // [b][o][k] padded rows

__device__ __forceinline__ void ffma2(unsigned long long &d, unsigned long long a, unsigned long long b) {
    asm("fma.rn.f32x2 %0, %1, %2, %0;" : "+l"(d) : "l"(a), "l"(b));
}
__device__ __forceinline__ unsigned long long dup2(float v) {
    unsigned long long r; asm("mov.b64 %0, {%1, %1};" : "=l"(r) : "f"(v)); return r;
}
__device__ __forceinline__ float2 unpk(unsigned long long v) {
    float2 r; asm("mov.b64 {%0, %1}, %2;" : "=f"(r.x), "=f"(r.y) : "l"(v)); return r;
}

// ---------------------------------------------------------------------------
// K1: pooled psi/phi convs -> q[b,m], z[b,o,m]; also s[b,n] (theta folded).
// grid 512 (= B * 128 tiles of 16 m), block 128.  (R10 version)
// ---------------------------------------------------------------------------
__global__ __launch_bounds__(128) void k1_zq(
    const float* __restrict__ x,
    const float* __restrict__ psi_w, const float* __restrict__ psi_b,
    const float* __restrict__ theta_w, const float* __restrict__ theta_b,
    const float* __restrict__ phi_w, const float* __restrict__ phi_b,
    const float* __restrict__ h0_w, const float* __restrict__ h1_w,
    const float* __restrict__ h2_w, const float* __restrict__ W_w)
{
    __shared__ __align__(16) float  xs[64*2*32];       // [c][r][tl]
    __shared__ __align__(16) float2 wpsp[64*18];       // [c][j] pairs (j, j+16)
    __shared__ __align__(16) float2 wphp[64*18];
    __shared__ __align__(16) float2 Wwsp[64*18];       // [o][j] pairs
    __shared__ __align__(16) float2 psi_sp[16*17];     // [ml][j] pairs
    __shared__ float phi_part[16*8];
    __shared__ float uS[64];
    __shared__ float tbS;

    int tid = threadIdx.x;
    int bid = blockIdx.x;
    int b   = bid >> 7;
    int g   = bid & 127;
    int fm  = g >> 2;
    int tm0 = (g & 3) << 4;
    int f0 = fm << 1;
    int t0 = tm0 << 1;

    const float* xb = x + (size_t)b*CC*NN;
    const float4* xb4 = (const float4*)xb;
    float4* xs4 = (float4*)xs;
    // 1024 float4 total: cc (64) x r (2) x tl4 (8)
    #pragma unroll
    for (int rep = 0; rep < 8; rep++) {
        int u = rep*128 + tid;
        int cc = u >> 4, r = (u >> 3) & 1, tl4 = u & 7;
        xs4[u] = xb4[(cc*FF + f0 + r)*32 + (t0 >> 2) + tl4];
    }
    #pragma unroll
    for (int rep = 0; rep < 8; rep++) {
        int u = rep*128 + tid;
        int j = u >> 6, cc = u & 63;
        wpsp[cc*18 + j] = make_float2(psi_w[j*CC + cc], psi_w[(j+16)*CC + cc]);
        wphp[cc*18 + j] = make_float2(phi_w[j*CC + cc], phi_w[(j+16)*CC + cc]);
    }
    #pragma unroll
    for (int rep = 0; rep < 8; rep++) {
        int u = rep*128 + tid;
        int o = u >> 4, j = u & 15;
        Wwsp[o*18 + j] = make_float2(W_w[o*33 + j], W_w[o*33 + j + 16]);
    }
    if (tid < 64) {
        float acc = 0.f;
        #pragma unroll
        for (int i = 0; i < 32; i++) acc = fmaf(h0_w[i], theta_w[i*CC + tid], acc);
        uS[tid] = acc;
    } else if (tid == 64) {
        float acc = 0.f;
        #pragma unroll
        for (int i = 0; i < 32; i++) acc = fmaf(h0_w[i], theta_b[i], acc);
        tbS = acc;
    }
    __syncthreads();

    // register-blocked pooled conv: 2 j-pairs x 4 pool positions x 2 convs
    int ml = tid >> 3, ig = tid & 7;
    unsigned long long ap[8], af[8];
    #pragma unroll
    for (int i = 0; i < 8; i++) { ap[i] = 0ull; af[i] = 0ull; }
    const float2* wp0 = wpsp + ig*2;
    const float2* wf0 = wphp + ig*2;
    const float*  xr0 = xs + 2*ml;
    #pragma unroll 8
    for (int cc = 0; cc < 64; cc++) {
        ulonglong2 wP = *(const ulonglong2*)(wp0 + cc*18);
        ulonglong2 wF = *(const ulonglong2*)(wf0 + cc*18);
        float2 v0 = *(const float2*)(xr0 + cc*64);
        float2 v1 = *(const float2*)(xr0 + cc*64 + 32);
        unsigned long long d00 = dup2(v0.x), d01 = dup2(v0.y);
        unsigned long long d10 = dup2(v1.x), d11 = dup2(v1.y);
        ffma2(ap[0], wP.x, d00); ffma2(ap[1], wP.x, d01); ffma2(ap[2], wP.x, d10); ffma2(ap[3], wP.x, d11);
        ffma2(ap[4], wP.y, d00); ffma2(ap[5], wP.y, d01); ffma2(ap[6], wP.y, d10); ffma2(ap[7], wP.y, d11);
        ffma2(af[0], wF.x, d00); ffma2(af[1], wF.x, d01); ffma2(af[2], wF.x, d10); ffma2(af[3], wF.x, d11);
        ffma2(af[4], wF.y, d00); ffma2(af[5], wF.y, d01); ffma2(af[6], wF.y, d10); ffma2(af[7], wF.y, d11);
    }

    float qpart = 0.f;
    #pragma unroll
    for (int jj = 0; jj < 2; jj++) {
        int j = ig*2 + jj;
        float2 p0 = unpk(ap[jj*4+0]), p1 = unpk(ap[jj*4+1]);
        float2 p2 = unpk(ap[jj*4+2]), p3 = unpk(ap[jj*4+3]);
        float plo = fmaxf(fmaxf(p0.x,p1.x), fmaxf(p2.x,p3.x)) + psi_b[j];
        float phv = fmaxf(fmaxf(p0.y,p1.y), fmaxf(p2.y,p3.y)) + psi_b[j+16];
        psi_sp[ml*17 + j] = make_float2(plo, phv);
        float2 q0 = unpk(af[jj*4+0]), q1 = unpk(af[jj*4+1]);
        float2 q2 = unpk(af[jj*4+2]), q3 = unpk(af[jj*4+3]);
        float flo = fmaxf(fmaxf(q0.x,q1.x), fmaxf(q2.x,q3.x)) + phi_b[j];
        float fhi = fmaxf(fmaxf(q0.y,q1.y), fmaxf(q2.y,q3.y)) + phi_b[j+16];
        qpart = fmaf(h1_w[j], flo, qpart);
        qpart = fmaf(h1_w[j+16], fhi, qpart);
    }
    phi_part[ml*8 + ig] = qpart;

    // s[n] for the 64 n's this tile covers
    if (tid < 64) {
        int r_ = tid >> 5, tl = tid & 31;
        const float* xr = xs + r_*32 + tl;
        float s = tbS;
        #pragma unroll 16
        for (int cc = 0; cc < 64; cc++) s = fmaf(uS[cc], xr[cc*64], s);
        int fg = f0 + r_, tg = t0 + tl;
        s += h2_w[0]*((float)fg*(1.f/63.f)) + h2_w[1]*((float)tg*(1.f/127.f));
        g_s[b*NN + fg*TT + tg] = s;
    }
    __syncthreads();

    if (tid < 16) {
        const float* pp = phi_part + tid*8;
        float acc = ((pp[0]+pp[1]) + (pp[2]+pp[3])) + ((pp[4]+pp[5]) + (pp[6]+pp[7]));
        int tmm = tm0 + tid;
        float bp = h2_w[0]*((float)fm*(1.f/31.f)) + h2_w[1]*((float)tmm*(1.f/63.f));
        g_q[b*MM + fm*64 + tmm] = acc - bp;
    }

    // z[o][m] = sum_j W-pairs . psi-pairs
    const unsigned long long* Ww64 = (const unsigned long long*)Wwsp;
    const unsigned long long* Ps64 = (const unsigned long long*)psi_sp;
    float* zout = g_z + (size_t)b*CC*MM + fm*64 + tm0;
    #pragma unroll
    for (int rep = 0; rep < 8; rep++) {
        int task = rep*128 + tid;
        int o = task >> 4, mlz = task & 15;
        unsigned long long acc = 0ull;
        #pragma unroll
        for (int j = 0; j < 16; j++)
            ffma2(acc, Ww64[o*18 + j], Ps64[mlz*17 + j]);
        float2 rr = unpk(acc);
        zout[(size_t)o*MM + mlz] = rr.x + rr.y;
    }
}

// ---------------------------------------------------------------------------
// K2: parallel rank-sort of q. grid 128 (= B*32 segments of 64 elems), block 256.
// ---------------------------------------------------------------------------
__global__ __launch_bounds__(256) void k2_rank()
{
    __shared__ __align__(16) unsigned ordS[MM];
    __shared__ float qfS[MM];
    int bid = blockIdx.x;
    int b   = bid >> 5;
    int seg = bid & 31;
    int tid = threadIdx.x;

    cudaGridDependencySynchronize();

    #pragma unroll
    for (int rep = 0; rep < 8; rep++) {
        int i = rep*256 + tid;
        float f = g_q[b*MM + i];
        unsigned u = __float_as_uint(f);
        u ^= (((int)u) < 0) ? 0xFFFFFFFFu : 0x80000000u;
        ordS[i] = u; qfS[i] = f;
    }
    __syncthreads();

    int el = tid >> 2;
    int part = tid & 3;
    int e = seg*64 + el;
    unsigned ki = ordS[e];
    int cnt = 0;
    const uint4* basep = (const uint4*)(ordS + part*512);
    #pragma unroll 8
    for (int i = 0; i < 128; i++) {
        uint4 v = basep[i];
        int j0 = part*512 + i*4;
        cnt += (int)(v.x < ki) | ((v.x == ki) & (j0+0 < e));
        cnt += (int)(v.y < ki) | ((v.y == ki) & (j0+1 < e));
        cnt += (int)(v.z < ki) | ((v.z == ki) & (j0+2 < e));
        cnt += (int)(v.w < ki) | ((v.w == ki) & (j0+3 < e));
    }
    cnt += __shfl_down_sync(0xFFFFFFFFu, cnt, 2);
    cnt += __shfl_down_sync(0xFFFFFFFFu, cnt, 1);
    if (part == 0) {
        g_qs[b*MM + cnt] = qfS[e];
        g_perm[b*MM + cnt] = e;
    }
}

// ---------------------------------------------------------------------------
// K3: suffix sums pre-scaled by As[o] (coalesced [b][o][k] stores) + binary
// searches for this block's n-chunk, packed into g_sk.
// grid 256 (= B*C), block 256.
// ---------------------------------------------------------------------------
__global__ __launch_bounds__(256) void k3_scan(
    const float* __restrict__ bn_g, const float* __restrict__ bn_v)
{
    __shared__ float zS[MM];
    __shared__ float qsS[MM];
    __shared__ int   pS[MM];
    __shared__ float wtP[8], wtQ[8];

    int bo = blockIdx.x;
    int b = bo >> 6, o = bo & 63;
    int t = threadIdx.x, lane = t & 31, w = t >> 5;

    float As = bn_g[o]*rsqrtf(bn_v[o] + EPSF)*(1.0f/(float)MM);

    cudaGridDependencySynchronize();

    const float* zrow = g_z + ((size_t)b*CC + o)*MM;
    #pragma unroll
    for (int rep = 0; rep < 8; rep++) {
        int i = rep*256 + t;
        zS[i] = zrow[i]; qsS[i] = g_qs[b*MM + i]; pS[i] = g_perm[b*MM + i];
    }
    __syncthreads();

    // binary searches for n-chunk [o*128, o*128+128): first k with qs[k] > -s
    if (t < 128) {
        int n = o*128 + t;
        float sv = g_s[b*NN + n];
        float keyv = -sv;
        int lo = 0, hi = MM;
        while (lo < hi) { int mid = (lo + hi) >> 1; if (qsS[mid] > keyv) hi = mid; else lo = mid + 1; }
        g_sk[b*NN + n] = make_float2(sv, __int_as_float(lo));
    }

    float vP[8], vQ[8];
    int base = t*8;
    float sp = 0.f, sq = 0.f;
    #pragma unroll
    for (int e = 7; e >= 0; e--) {
        float zv = zS[pS[base + e]];
        sp += zv; sq = fmaf(qsS[base + e], zv, sq);
        vP[e] = sp; vQ[e] = sq;
    }
    float isp = sp, isq = sq;
    #pragma unroll
    for (int d = 1; d < 32; d <<= 1) {
        float tp = __shfl_down_sync(0xFFFFFFFFu, isp, d);
        float tq = __shfl_down_sync(0xFFFFFFFFu, isq, d);
        if (lane + d < 32) { isp += tp; isq += tq; }
    }
    if (lane == 0) { wtP[w] = isp; wtQ[w] = isq; }
    __syncthreads();
    float offP = isp - sp, offQ = isq - sq;
    #pragma unroll
    for (int w2 = 0; w2 < 8; w2++) if (w2 > w) { offP += wtP[w2]; offQ += wtQ[w2]; }

    float2* outp = g_PQ + ((size_t)b*CC + o)*(MM+2);
    #pragma unroll
    for (int e = 0; e < 8; e++)
        outp[base + e] = make_float2((vP[e]+offP)*As, (vQ[e]+offQ)*As);
    if (t == 0) { outp[MM] = make_float2(0.f, 0.f); outp[MM+1] = make_float2(0.f, 0.f); }
}

// ---------------------------------------------------------------------------
// K4: per (b, o, n-half): stage PQ row once, float4 streamed epilogue.
// grid 512, block 256, smem 16.4KB.
// ---------------------------------------------------------------------------
__global__ __launch_bounds__(256) void k4_apply(
    const float* __restrict__ x, const float* __restrict__ W_b,
    const float* __restrict__ bn_g, const float* __restrict__ bn_b,
    const float* __restrict__ bn_m, const float* __restrict__ bn_v,
    float* __restrict__ out)
{
    __shared__ __align__(16) float2 row[MM+2];

    int tid = threadIdx.x;
    int bid = blockIdx.x;
    int b = bid >> 7;
    int rem = bid & 127;
    int o = rem >> 1, half = rem & 1;

    float inv = bn_g[o]*rsqrtf(bn_v[o] + EPSF);
    float Ds = fmaf(W_b[o], inv, bn_b[o] - bn_m[o]*inv);

    cudaGridDependencySynchronize();

    const float4* PQ4 = (const float4*)(g_PQ + ((size_t)b*CC + o)*(MM+2));
    float4* row4 = (float4*)row;
    #pragma unroll
    for (int rep = 0; rep < 4; rep++) row4[rep*256 + tid] = PQ4[rep*256 + tid];
    if (tid == 0) row4[1024] = PQ4[1024];
    __syncthreads();

    const float4* sk4 = (const float4*)(g_sk + (size_t)b*NN);
    const float4* x4  = (const float4*)(x   + ((size_t)b*CC + o)*NN);
    float4*       o4  = (float4*)(out + ((size_t)b*CC + o)*NN);

    int gbase = half*1024;
    #pragma unroll
    for (int it = 0; it < 4; it++) {
        int idx = gbase + it*256 + tid;         // group of 4 n
        float4 xa  = x4[idx];
        float4 skA = sk4[idx*2];
        float4 skB = sk4[idx*2 + 1];
        float2 r0 = row[__float_as_int(skA.y)];
        float2 r1 = row[__float_as_int(skA.w)];
        float2 r2 = row[__float_as_int(skB.y)];
        float2 r3 = row[__float_as_int(skB.w)];
        float4 r;
        r.x = fmaf(skA.x, r0.x, r0.y) + Ds + xa.x;
        r.y = fmaf(skA.z, r1.x, r1.y) + Ds + xa.y;
        r.z = fmaf(skB.x, r2.x, r2.y) + Ds + xa.z;
        r.w = fmaf(skB.z, r3.x, r3.y) + Ds + xa.w;
        o4[idx] = r;
    }
}

// ---------------------------------------------------------------------------
extern "C" void kernel_launch(void* const* d_in, const int* in_sizes, int n_in,
                              void* d_out, int out_size)
{
    const float* x       = (const float*)d_in[0];
    const float* psi_w   = (const float*)d_in[1];
    const float* psi_b   = (const float*)d_in[2];
    const float* theta_w = (const float*)d_in[3];
    const float* theta_b = (const float*)d_in[4];
    const float* phi_w   = (const float*)d_in[5];
    const float* phi_b   = (const float*)d_in[6];
    const float* h0_w    = (const float*)d_in[7];
    const float* h1_w    = (const float*)d_in[8];
    const float* h2_w    = (const float*)d_in[9];
    const float* W_w     = (const float*)d_in[10];
    const float* W_b     = (const float*)d_in[11];
    const float* bn_g    = (const float*)d_in[12];
    const float* bn_b    = (const float*)d_in[13];
    const float* bn_m    = (const float*)d_in[14];
    const float* bn_v    = (const float*)d_in[15];
    float* out = (float*)d_out;

    k1_zq<<<512, 128>>>(x, psi_w, psi_b, theta_w, theta_b, phi_w, phi_b,
                        h0_w, h1_w, h2_w, W_w);

    cudaLaunchAttribute attr[1];
    attr[0].id = cudaLaunchAttributeProgrammaticStreamSerialization;
    attr[0].val.programmaticStreamSerializationAllowed = 1;

    {
        cudaLaunchConfig_t cfg = {};
        cfg.gridDim = dim3(128); cfg.blockDim = dim3(256);
        cfg.attrs = attr; cfg.numAttrs = 1;
        cudaLaunchKernelEx(&cfg, k2_rank);
    }
    {
        cudaLaunchConfig_t cfg = {};
        cfg.gridDim = dim3(256); cfg.blockDim = dim3(256);
        cfg.attrs = attr; cfg.numAttrs = 1;
        cudaLaunchKernelEx(&cfg, k3_scan, bn_g, bn_v);
    }
    {
        cudaLaunchConfig_t cfg = {};
        cfg.gridDim = dim3(512); cfg.blockDim = dim3(256);
        cfg.attrs = attr; cfg.numAttrs = 1;
        cudaLaunchKernelEx(&cfg, k4_apply, x, W_b, bn_g, bn_b, bn_m, bn_v, out);
    }
}

// round 14
// speedup vs baseline: 1.6049x; 1.6049x over previous
#include <cuda_runtime.h>
#include <cuda_bf16.h>
#include <cstdint>

#define BB 4
#define CC 64
#define FF 64
#define TT 128
#define IC 32
#define NN 8192
#define MM 2048
#define EPSF 1e-5f

// Scratch (device globals; allocation forbidden)
__device__ float  g_q[BB*MM];
__device__ float  g_qs[BB*MM];
__device__ int    g_perm[BB*MM];
__device__ float  g_z[BB*CC*MM];
__device__ float  g_s[BB*NN];
__device__ float2 g_sk[BB*NN];            // (s[n], bitcast k[n])
__device__ float2 g_PQ[BB*CC*(MM+2)];     // [b][o][k] padded rows

__device__ __forceinline__ void ffma2(unsigned long long &d, unsigned long long a, unsigned long long b) {
    asm("fma.rn.f32x2 %0, %1, %2, %0;" : "+l"(d) : "l"(a), "l"(b));
}
__device__ __forceinline__ unsigned long long dup2(float v) {
    unsigned long long r; asm("mov.b64 %0, {%1, %1};" : "=l"(r) : "f"(v)); return r;
}
__device__ __forceinline__ float2 unpk(unsigned long long v) {
    float2 r; asm("mov.b64 {%0, %1}, %2;" : "=f"(r.x), "=f"(r.y) : "l"(v)); return r;
}

// ---------------------------------------------------------------------------
// K1: pooled psi/phi convs -> q[b,m], z[b,o,m]; also s[b,n] (theta folded).
// grid 512 (= B * 128 tiles of 16 m), block 128.
// ---------------------------------------------------------------------------
__global__ __launch_bounds__(128) void k1_zq(
    const float* __restrict__ x,
    const float* __restrict__ psi_w, const float* __restrict__ psi_b,
    const float* __restrict__ theta_w, const float* __restrict__ theta_b,
    const float* __restrict__ phi_w, const float* __restrict__ phi_b,
    const float* __restrict__ h0_w, const float* __restrict__ h1_w,
    const float* __restrict__ h2_w, const float* __restrict__ W_w)
{
    __shared__ __align__(16) float  xs[64*2*32];       // [c][r][tl]
    __shared__ __align__(16) float2 wpsp[64*18];       // [c][j] pairs (j, j+16)
    __shared__ __align__(16) float2 wphp[64*18];
    __shared__ __align__(16) float2 Wwsp[64*18];       // [o][j] pairs
    __shared__ __align__(16) float2 psi_sp[16*17];     // [ml][j] pairs
    __shared__ float phi_part[16*8];
    __shared__ float uS[64];
    __shared__ float tbS;

    int tid = threadIdx.x;
    int bid = blockIdx.x;
    int b   = bid >> 7;
    int g   = bid & 127;
    int fm  = g >> 2;
    int tm0 = (g & 3) << 4;
    int f0 = fm << 1;
    int t0 = tm0 << 1;

    const float* xb = x + (size_t)b*CC*NN;
    const float4* xb4 = (const float4*)xb;
    float4* xs4 = (float4*)xs;
    // 1024 float4 total: cc (64) x r (2) x tl4 (8)
    #pragma unroll
    for (int rep = 0; rep < 8; rep++) {
        int u = rep*128 + tid;
        int cc = u >> 4, r = (u >> 3) & 1, tl4 = u & 7;
        xs4[u] = xb4[(cc*FF + f0 + r)*32 + (t0 >> 2) + tl4];
    }
    #pragma unroll
    for (int rep = 0; rep < 8; rep++) {
        int u = rep*128 + tid;
        int j = u >> 6, cc = u & 63;
        wpsp[cc*18 + j] = make_float2(psi_w[j*CC + cc], psi_w[(j+16)*CC + cc]);
        wphp[cc*18 + j] = make_float2(phi_w[j*CC + cc], phi_w[(j+16)*CC + cc]);
    }
    #pragma unroll
    for (int rep = 0; rep < 8; rep++) {
        int u = rep*128 + tid;
        int o = u >> 4, j = u & 15;
        Wwsp[o*18 + j] = make_float2(W_w[o*33 + j], W_w[o*33 + j + 16]);
    }
    if (tid < 64) {
        float acc = 0.f;
        #pragma unroll
        for (int i = 0; i < 32; i++) acc = fmaf(h0_w[i], theta_w[i*CC + tid], acc);
        uS[tid] = acc;
    } else if (tid == 64) {
        float acc = 0.f;
        #pragma unroll
        for (int i = 0; i < 32; i++) acc = fmaf(h0_w[i], theta_b[i], acc);
        tbS = acc;
    }
    __syncthreads();

    // register-blocked pooled conv: 2 j-pairs x 4 pool positions x 2 convs
    int ml = tid >> 3, ig = tid & 7;
    unsigned long long ap[8], af[8];
    #pragma unroll
    for (int i = 0; i < 8; i++) { ap[i] = 0ull; af[i] = 0ull; }
    const float2* wp0 = wpsp + ig*2;
    const float2* wf0 = wphp + ig*2;
    const float*  xr0 = xs + 2*ml;
    #pragma unroll 8
    for (int cc = 0; cc < 64; cc++) {
        ulonglong2 wP = *(const ulonglong2*)(wp0 + cc*18);
        ulonglong2 wF = *(const ulonglong2*)(wf0 + cc*18);
        float2 v0 = *(const float2*)(xr0 + cc*64);
        float2 v1 = *(const float2*)(xr0 + cc*64 + 32);
        unsigned long long d00 = dup2(v0.x), d01 = dup2(v0.y);
        unsigned long long d10 = dup2(v1.x), d11 = dup2(v1.y);
        ffma2(ap[0], wP.x, d00); ffma2(ap[1], wP.x, d01); ffma2(ap[2], wP.x, d10); ffma2(ap[3], wP.x, d11);
        ffma2(ap[4], wP.y, d00); ffma2(ap[5], wP.y, d01); ffma2(ap[6], wP.y, d10); ffma2(ap[7], wP.y, d11);
        ffma2(af[0], wF.x, d00); ffma2(af[1], wF.x, d01); ffma2(af[2], wF.x, d10); ffma2(af[3], wF.x, d11);
        ffma2(af[4], wF.y, d00); ffma2(af[5], wF.y, d01); ffma2(af[6], wF.y, d10); ffma2(af[7], wF.y, d11);
    }

    float qpart = 0.f;
    #pragma unroll
    for (int jj = 0; jj < 2; jj++) {
        int j = ig*2 + jj;
        float2 p0 = unpk(ap[jj*4+0]), p1 = unpk(ap[jj*4+1]);
        float2 p2 = unpk(ap[jj*4+2]), p3 = unpk(ap[jj*4+3]);
        float plo = fmaxf(fmaxf(p0.x,p1.x), fmaxf(p2.x,p3.x)) + psi_b[j];
        float phv = fmaxf(fmaxf(p0.y,p1.y), fmaxf(p2.y,p3.y)) + psi_b[j+16];
        psi_sp[ml*17 + j] = make_float2(plo, phv);
        float2 q0 = unpk(af[jj*4+0]), q1 = unpk(af[jj*4+1]);
        float2 q2 = unpk(af[jj*4+2]), q3 = unpk(af[jj*4+3]);
        float flo = fmaxf(fmaxf(q0.x,q1.x), fmaxf(q2.x,q3.x)) + phi_b[j];
        float fhi = fmaxf(fmaxf(q0.y,q1.y), fmaxf(q2.y,q3.y)) + phi_b[j+16];
        qpart = fmaf(h1_w[j], flo, qpart);
        qpart = fmaf(h1_w[j+16], fhi, qpart);
    }
    phi_part[ml*8 + ig] = qpart;

    // s[n] for the 64 n's this tile covers
    if (tid < 64) {
        int r_ = tid >> 5, tl = tid & 31;
        const float* xr = xs + r_*32 + tl;
        float s = tbS;
        #pragma unroll 16
        for (int cc = 0; cc < 64; cc++) s = fmaf(uS[cc], xr[cc*64], s);
        int fg = f0 + r_, tg = t0 + tl;
        s += h2_w[0]*((float)fg*(1.f/63.f)) + h2_w[1]*((float)tg*(1.f/127.f));
        g_s[b*NN + fg*TT + tg] = s;
    }
    __syncthreads();

    if (tid < 16) {
        const float* pp = phi_part + tid*8;
        float acc = ((pp[0]+pp[1]) + (pp[2]+pp[3])) + ((pp[4]+pp[5]) + (pp[6]+pp[7]));
        int tmm = tm0 + tid;
        float bp = h2_w[0]*((float)fm*(1.f/31.f)) + h2_w[1]*((float)tmm*(1.f/63.f));
        g_q[b*MM + fm*64 + tmm] = acc - bp;
    }

    // z[o][m] = sum_j W-pairs . psi-pairs
    const unsigned long long* Ww64 = (const unsigned long long*)Wwsp;
    const unsigned long long* Ps64 = (const unsigned long long*)psi_sp;
    float* zout = g_z + (size_t)b*CC*MM + fm*64 + tm0;
    #pragma unroll
    for (int rep = 0; rep < 8; rep++) {
        int task = rep*128 + tid;
        int o = task >> 4, mlz = task & 15;
        unsigned long long acc = 0ull;
        #pragma unroll
        for (int j = 0; j < 16; j++)
            ffma2(acc, Ww64[o*18 + j], Ps64[mlz*17 + j]);
        float2 rr = unpk(acc);
        zout[(size_t)o*MM + mlz] = rr.x + rr.y;
    }
}

// ---------------------------------------------------------------------------
// K2: parallel rank-sort of q. grid 128 (= B*32 segments of 64 elems), block 256.
// ---------------------------------------------------------------------------
__global__ __launch_bounds__(256) void k2_rank()
{
    __shared__ __align__(16) unsigned ordS[MM];
    __shared__ float qfS[MM];
    int bid = blockIdx.x;
    int b   = bid >> 5;
    int seg = bid & 31;
    int tid = threadIdx.x;

    cudaGridDependencySynchronize();

    #pragma unroll
    for (int rep = 0; rep < 8; rep++) {
        int i = rep*256 + tid;
        float f = g_q[b*MM + i];
        unsigned u = __float_as_uint(f);
        u ^= (((int)u) < 0) ? 0xFFFFFFFFu : 0x80000000u;
        ordS[i] = u; qfS[i] = f;
    }
    __syncthreads();

    int el = tid >> 2;
    int part = tid & 3;
    int e = seg*64 + el;
    unsigned ki = ordS[e];
    int cnt = 0;
    const uint4* basep = (const uint4*)(ordS + part*512);
    #pragma unroll 8
    for (int i = 0; i < 128; i++) {
        uint4 v = basep[i];
        int j0 = part*512 + i*4;
        cnt += (int)(v.x < ki) | ((v.x == ki) & (j0+0 < e));
        cnt += (int)(v.y < ki) | ((v.y == ki) & (j0+1 < e));
        cnt += (int)(v.z < ki) | ((v.z == ki) & (j0+2 < e));
        cnt += (int)(v.w < ki) | ((v.w == ki) & (j0+3 < e));
    }
    cnt += __shfl_down_sync(0xFFFFFFFFu, cnt, 2);
    cnt += __shfl_down_sync(0xFFFFFFFFu, cnt, 1);
    if (part == 0) {
        g_qs[b*MM + cnt] = qfS[e];
        g_perm[b*MM + cnt] = e;
    }
}

// ---------------------------------------------------------------------------
// K3: suffix sums pre-scaled by As[o] (coalesced [b][o][k] stores) + binary
// searches for this block's n-chunk, packed into g_sk.
// grid 256 (= B*C), block 256.
// ---------------------------------------------------------------------------
__global__ __launch_bounds__(256) void k3_scan(
    const float* __restrict__ bn_g, const float* __restrict__ bn_v)
{
    __shared__ float zS[MM];
    __shared__ float qsS[MM];
    __shared__ int   pS[MM];
    __shared__ float wtP[8], wtQ[8];

    int bo = blockIdx.x;
    int b = bo >> 6, o = bo & 63;
    int t = threadIdx.x, lane = t & 31, w = t >> 5;

    float As = bn_g[o]*rsqrtf(bn_v[o] + EPSF)*(1.0f/(float)MM);

    cudaGridDependencySynchronize();

    const float* zrow = g_z + ((size_t)b*CC + o)*MM;
    #pragma unroll
    for (int rep = 0; rep < 8; rep++) {
        int i = rep*256 + t;
        zS[i] = zrow[i]; qsS[i] = g_qs[b*MM + i]; pS[i] = g_perm[b*MM + i];
    }
    __syncthreads();

    // binary searches for n-chunk [o*128, o*128+128): first k with qs[k] > -s
    if (t < 128) {
        int n = o*128 + t;
        float sv = g_s[b*NN + n];
        float keyv = -sv;
        int lo = 0, hi = MM;
        while (lo < hi) { int mid = (lo + hi) >> 1; if (qsS[mid] > keyv) hi = mid; else lo = mid + 1; }
        g_sk[b*NN + n] = make_float2(sv, __int_as_float(lo));
    }

    float vP[8], vQ[8];
    int base = t*8;
    float sp = 0.f, sq = 0.f;
    #pragma unroll
    for (int e = 7; e >= 0; e--) {
        float zv = zS[pS[base + e]];
        sp += zv; sq = fmaf(qsS[base + e], zv, sq);
        vP[e] = sp; vQ[e] = sq;
    }
    float isp = sp, isq = sq;
    #pragma unroll
    for (int d = 1; d < 32; d <<= 1) {
        float tp = __shfl_down_sync(0xFFFFFFFFu, isp, d);
        float tq = __shfl_down_sync(0xFFFFFFFFu, isq, d);
        if (lane + d < 32) { isp += tp; isq += tq; }
    }
    if (lane == 0) { wtP[w] = isp; wtQ[w] = isq; }
    __syncthreads();
    float offP = isp - sp, offQ = isq - sq;
    #pragma unroll
    for (int w2 = 0; w2 < 8; w2++) if (w2 > w) { offP += wtP[w2]; offQ += wtQ[w2]; }

    float2* outp = g_PQ + ((size_t)b*CC + o)*(MM+2);
    #pragma unroll
    for (int e = 0; e < 8; e++)
        outp[base + e] = make_float2((vP[e]+offP)*As, (vQ[e]+offQ)*As);
    if (t == 0) { outp[MM] = make_float2(0.f, 0.f); outp[MM+1] = make_float2(0.f, 0.f); }
}

// ---------------------------------------------------------------------------
// K4: per (b, o): stage PQ row once, full-n float4 streamed epilogue.
// grid 256, block 256, smem 16.4KB.
// ---------------------------------------------------------------------------
__global__ __launch_bounds__(256) void k4_apply(
    const float* __restrict__ x, const float* __restrict__ W_b,
    const float* __restrict__ bn_g, const float* __restrict__ bn_b,
    const float* __restrict__ bn_m, const float* __restrict__ bn_v,
    float* __restrict__ out)
{
    __shared__ __align__(16) float2 row[MM+2];

    int tid = threadIdx.x;
    int bid = blockIdx.x;
    int b = bid >> 6;
    int o = bid & 63;

    float inv = bn_g[o]*rsqrtf(bn_v[o] + EPSF);
    float Ds = fmaf(W_b[o], inv, bn_b[o] - bn_m[o]*inv);

    cudaGridDependencySynchronize();

    const float4* PQ4 = (const float4*)(g_PQ + ((size_t)b*CC + o)*(MM+2));
    float4* row4 = (float4*)row;
    #pragma unroll
    for (int rep = 0; rep < 4; rep++) row4[rep*256 + tid] = PQ4[rep*256 + tid];
    if (tid == 0) row4[1024] = PQ4[1024];
    __syncthreads();

    const float4* sk4 = (const float4*)(g_sk + (size_t)b*NN);
    const float4* x4  = (const float4*)(x   + ((size_t)b*CC + o)*NN);
    float4*       o4  = (float4*)(out + ((size_t)b*CC + o)*NN);

    #pragma unroll
    for (int it = 0; it < 8; it++) {
        int idx = it*256 + tid;                 // group of 4 n
        float4 xa  = x4[idx];
        float4 skA = sk4[idx*2];
        float4 skB = sk4[idx*2 + 1];
        float2 r0 = row[__float_as_int(skA.y)];
        float2 r1 = row[__float_as_int(skA.w)];
        float2 r2 = row[__float_as_int(skB.y)];
        float2 r3 = row[__float_as_int(skB.w)];
        float4 r;
        r.x = fmaf(skA.x, r0.x, r0.y) + Ds + xa.x;
        r.y = fmaf(skA.z, r1.x, r1.y) + Ds + xa.y;
        r.z = fmaf(skB.x, r2.x, r2.y) + Ds + xa.z;
        r.w = fmaf(skB.z, r3.x, r3.y) + Ds + xa.w;
        o4[idx] = r;
    }
}

// ---------------------------------------------------------------------------
extern "C" void kernel_launch(void* const* d_in, const int* in_sizes, int n_in,
                              void* d_out, int out_size)
{
    const float* x       = (const float*)d_in[0];
    const float* psi_w   = (const float*)d_in[1];
    const float* psi_b   = (const float*)d_in[2];
    const float* theta_w = (const float*)d_in[3];
    const float* theta_b = (const float*)d_in[4];
    const float* phi_w   = (const float*)d_in[5];
    const float* phi_b   = (const float*)d_in[6];
    const float* h0_w    = (const float*)d_in[7];
    const float* h1_w    = (const float*)d_in[8];
    const float* h2_w    = (const float*)d_in[9];
    const float* W_w     = (const float*)d_in[10];
    const float* W_b     = (const float*)d_in[11];
    const float* bn_g    = (const float*)d_in[12];
    const float* bn_b    = (const float*)d_in[13];
    const float* bn_m    = (const float*)d_in[14];
    const float* bn_v    = (const float*)d_in[15];
    float* out = (float*)d_out;

    k1_zq<<<512, 128>>>(x, psi_w, psi_b, theta_w, theta_b, phi_w, phi_b,
                        h0_w, h1_w, h2_w, W_w);

    cudaLaunchAttribute attr[1];
    attr[0].id = cudaLaunchAttributeProgrammaticStreamSerialization;
    attr[0].val.programmaticStreamSerializationAllowed = 1;

    {
        cudaLaunchConfig_t cfg = {};
        cfg.gridDim = dim3(128); cfg.blockDim = dim3(256);
        cfg.attrs = attr; cfg.numAttrs = 1;
        cudaLaunchKernelEx(&cfg, k2_rank);
    }
    {
        cudaLaunchConfig_t cfg = {};
        cfg.gridDim = dim3(256); cfg.blockDim = dim3(256);
        cfg.attrs = attr; cfg.numAttrs = 1;
        cudaLaunchKernelEx(&cfg, k3_scan, bn_g, bn_v);
    }
    {
        cudaLaunchConfig_t cfg = {};
        cfg.gridDim = dim3(256); cfg.blockDim = dim3(256);
        cfg.attrs = attr; cfg.numAttrs = 1;
        cudaLaunchKernelEx(&cfg, k4_apply, x, W_b, bn_g, bn_b, bn_m, bn_v, out);
    }
}